// round 1
// baseline (speedup 1.0000x reference)
#include <cuda_runtime.h>
#include <cuda_bf16.h>
#include <math.h>
#include <stdint.h>

// Problem constants
#define BB   32
#define NSZ  4096
#define DD   256
#define HH   4
#define DHD  64
#define LLV  6
#define NQS  512
#define NKS  1024
#define ATT_SCALE 0.125f   // 1/sqrt(64)

// ---------------------------------------------------------------------------
// Scratch (device globals; allocation-free rule)
// ---------------------------------------------------------------------------
__device__ float g_upd[(size_t)BB * NSZ * DD];   // working copy of update_tensor
__device__ float g_q  [(size_t)BB * NQS * DD];
__device__ float g_k  [(size_t)BB * NKS * DD];
__device__ float g_Qp [(size_t)BB * NQS * DD];
__device__ float g_Kp [(size_t)BB * NKS * DD];
__device__ float g_Vp [(size_t)BB * NKS * DD];
__device__ float g_ctx[(size_t)BB * NQS * DD];
__device__ float g_t1 [(size_t)BB * NQS * DD];
__device__ float g_h  [(size_t)BB * NQS * DD];
__device__ float g_gl [(size_t)BB * NQS * DD];
__device__ float g_f  [(size_t)BB * NQS * DD];
__device__ float g_res[(size_t)BB * NQS * DD];

// ---------------------------------------------------------------------------
// Utility kernels
// ---------------------------------------------------------------------------
__global__ void copy4_kernel(float* __restrict__ dst, const float* __restrict__ src, size_t n4) {
    size_t i = (size_t)blockIdx.x * blockDim.x + threadIdx.x;
    size_t stride = (size_t)gridDim.x * blockDim.x;
    const float4* s = (const float4*)src;
    float4* d = (float4*)dst;
    for (; i < n4; i += stride) d[i] = s[i];
}

__global__ void zero4_kernel(float* __restrict__ dst, size_t n4) {
    size_t i = (size_t)blockIdx.x * blockDim.x + threadIdx.x;
    size_t stride = (size_t)gridDim.x * blockDim.x;
    float4* d = (float4*)dst;
    float4 z = make_float4(0.f, 0.f, 0.f, 0.f);
    for (; i < n4; i += stride) d[i] = z;
}

// Block reduction over 256 threads (8 warps). red8 is 8-float smem scratch.
__device__ __forceinline__ float blk_sum(float v, float* red8) {
#pragma unroll
    for (int o = 16; o; o >>= 1) v += __shfl_xor_sync(0xffffffffu, v, o);
    __syncthreads();   // protect red8 from previous use
    if ((threadIdx.x & 31) == 0) red8[threadIdx.x >> 5] = v;
    __syncthreads();
    float s = 0.f;
#pragma unroll
    for (int i = 0; i < 8; i++) s += red8[i];
    return s;
}

// ---------------------------------------------------------------------------
// Gather + LayerNorm:  out[row,:] = LN(emb[idx] + upd[b, idx, :]) * s + b
// one block (256 threads) per output row; shift: log2(rows-per-batch)
// ---------------------------------------------------------------------------
__global__ void gather_ln_kernel(const float* __restrict__ emb,
                                 const int* __restrict__ idxs,
                                 const float* __restrict__ scale,
                                 const float* __restrict__ bias,
                                 const float* __restrict__ upd,
                                 float* __restrict__ out,
                                 int shift) {
    __shared__ float red[8];
    int row = blockIdx.x;
    int b = row >> shift;
    int i = row & ((1 << shift) - 1);
    int t = threadIdx.x;
    int idx = __ldg(&idxs[i]);
    float x = __ldg(&emb[(size_t)idx * DD + t]) + upd[((size_t)b * NSZ + idx) * DD + t];
    float m = blk_sum(x, red) * (1.0f / DD);
    float d = x - m;
    float v = blk_sum(d * d, red) * (1.0f / DD);
    out[(size_t)row * DD + t] = d * rsqrtf(v + 1e-5f) * __ldg(&scale[t]) + __ldg(&bias[t]);
}

// ---------------------------------------------------------------------------
// LayerNorm over rows of length 256
// ---------------------------------------------------------------------------
__global__ void ln_rows_kernel(const float* __restrict__ X,
                               const float* __restrict__ scale,
                               const float* __restrict__ bias,
                               float* __restrict__ out) {
    __shared__ float red[8];
    size_t row = blockIdx.x;
    int t = threadIdx.x;
    float x = X[row * DD + t];
    float m = blk_sum(x, red) * (1.0f / DD);
    float d = x - m;
    float v = blk_sum(d * d, red) * (1.0f / DD);
    out[row * DD + t] = d * rsqrtf(v + 1e-5f) * __ldg(&scale[t]) + __ldg(&bias[t]);
}

// res = LN( LN(Xa+Xb, s1,b1), s2,b2 )
__global__ void dln_rows_kernel(const float* __restrict__ Xa,
                                const float* __restrict__ Xb,
                                const float* __restrict__ s1, const float* __restrict__ bi1,
                                const float* __restrict__ s2, const float* __restrict__ bi2,
                                float* __restrict__ out) {
    __shared__ float red[8];
    size_t row = blockIdx.x;
    int t = threadIdx.x;
    float x = Xa[row * DD + t] + Xb[row * DD + t];
    float m = blk_sum(x, red) * (1.0f / DD);
    float d = x - m;
    float v = blk_sum(d * d, red) * (1.0f / DD);
    float y = d * rsqrtf(v + 1e-5f) * __ldg(&s1[t]) + __ldg(&bi1[t]);
    m = blk_sum(y, red) * (1.0f / DD);
    d = y - m;
    v = blk_sum(d * d, red) * (1.0f / DD);
    out[row * DD + t] = d * rsqrtf(v + 1e-5f) * __ldg(&s2[t]) + __ldg(&bi2[t]);
}

// ---------------------------------------------------------------------------
// GEMM: C[M,256] = A[M,256] @ W[256,256] (+bias)(+gelu)
// BM=BN=64, BK=32, 256 threads, 4x4 per thread. M must be multiple of 64.
// EPI: 0 = none, 1 = +bias, 2 = +bias then tanh-gelu
// ---------------------------------------------------------------------------
__device__ __forceinline__ float gelu_tanh(float x) {
    float x3 = x * x * x;
    return 0.5f * x * (1.0f + tanhf(0.7978845608028654f * (x + 0.044715f * x3)));
}

template <int EPI>
__global__ void gemm_k256(const float* __restrict__ A,
                          const float* __restrict__ W,
                          const float* __restrict__ bias,
                          float* __restrict__ C) {
    __shared__ __align__(16) float As[32][68];   // [k][m], padded
    __shared__ __align__(16) float Bs[32][64];   // [k][n]
    const int bm = blockIdx.x << 6;
    const int bn = blockIdx.y << 6;
    const int t = threadIdx.x;
    const int tx = t & 15, ty = t >> 4;
    const int arow = t >> 3, acv = (t & 7) << 2;   // A loader: 8 thr/row
    const int wrow = t >> 4, wcv = (t & 15) << 2;  // W loader: 16 thr/row

    float acc[4][4] = {};

    for (int k0 = 0; k0 < 256; k0 += 32) {
#pragma unroll
        for (int r = 0; r < 2; r++) {
            int m = arow + (r << 5);
            float4 v = *(const float4*)&A[(size_t)(bm + m) * 256 + k0 + acv];
            As[acv + 0][m] = v.x; As[acv + 1][m] = v.y;
            As[acv + 2][m] = v.z; As[acv + 3][m] = v.w;
        }
#pragma unroll
        for (int r = 0; r < 2; r++) {
            int kk = wrow + (r << 4);
            *(float4*)&Bs[kk][wcv] = *(const float4*)&W[(size_t)(k0 + kk) * 256 + bn + wcv];
        }
        __syncthreads();
#pragma unroll
        for (int kk = 0; kk < 32; kk++) {
            float4 a  = *(const float4*)&As[kk][ty << 2];
            float4 bv = *(const float4*)&Bs[kk][tx << 2];
            acc[0][0] += a.x * bv.x; acc[0][1] += a.x * bv.y; acc[0][2] += a.x * bv.z; acc[0][3] += a.x * bv.w;
            acc[1][0] += a.y * bv.x; acc[1][1] += a.y * bv.y; acc[1][2] += a.y * bv.z; acc[1][3] += a.y * bv.w;
            acc[2][0] += a.z * bv.x; acc[2][1] += a.z * bv.y; acc[2][2] += a.z * bv.z; acc[2][3] += a.z * bv.w;
            acc[3][0] += a.w * bv.x; acc[3][1] += a.w * bv.y; acc[3][2] += a.w * bv.z; acc[3][3] += a.w * bv.w;
        }
        __syncthreads();
    }

    float4 bz = make_float4(0.f, 0.f, 0.f, 0.f);
    if (EPI >= 1) bz = *(const float4*)&bias[bn + (tx << 2)];
#pragma unroll
    for (int i = 0; i < 4; i++) {
        float4 o;
        o.x = acc[i][0] + bz.x; o.y = acc[i][1] + bz.y;
        o.z = acc[i][2] + bz.z; o.w = acc[i][3] + bz.w;
        if (EPI == 2) {
            o.x = gelu_tanh(o.x); o.y = gelu_tanh(o.y);
            o.z = gelu_tanh(o.z); o.w = gelu_tanh(o.w);
        }
        *(float4*)&C[(size_t)(bm + (ty << 2) + i) * 256 + bn + (tx << 2)] = o;
    }
}

// ---------------------------------------------------------------------------
// Flash attention. Grid: (NQ/64, H, B), 256 threads.
// Q,K,V layouts: [B, n, 256] with head h at columns h*64..h*64+63.
// mask: [NQ, NK] floats for the current level; masked score -> -1e9 exactly.
// Dynamic smem: Qs,Ks,Vs,Ps each 64x68 floats = 69632 bytes total.
// ---------------------------------------------------------------------------
__global__ void attn64_kernel(const float* __restrict__ Qm,
                              const float* __restrict__ Km,
                              const float* __restrict__ Vm,
                              const float* __restrict__ mask,
                              float* __restrict__ ctx) {
    extern __shared__ float sm[];
    float* Qs = sm;                // 64*68
    float* Ks = Qs + 64 * 68;
    float* Vs = Ks + 64 * 68;
    float* Ps = Vs + 64 * 68;

    const int t = threadIdx.x;
    const int tx = t & 15, ty = t >> 4;
    const int b = blockIdx.z, h = blockIdx.y, q0 = blockIdx.x << 6;

    // load Q tile
    for (int v = t; v < 1024; v += 256) {
        int r = v >> 4, c = (v & 15) << 2;
        *(float4*)&Qs[r * 68 + c] =
            *(const float4*)&Qm[((size_t)(b * NQS + q0 + r)) * 256 + h * 64 + c];
    }

    float mrow[4], lrow[4], acc[4][4] = {};
#pragma unroll
    for (int i = 0; i < 4; i++) { mrow[i] = -3.0e38f; lrow[i] = 0.f; }

    for (int k0 = 0; k0 < NKS; k0 += 64) {
        __syncthreads();   // Qs ready (iter 0) / Ks,Vs,Ps free (later iters)
        for (int v = t; v < 1024; v += 256) {
            int r = v >> 4, c = (v & 15) << 2;
            size_t off = ((size_t)(b * NKS + k0 + r)) * 256 + h * 64 + c;
            *(float4*)&Ks[r * 68 + c] = *(const float4*)&Km[off];
            *(float4*)&Vs[r * 68 + c] = *(const float4*)&Vm[off];
        }
        __syncthreads();

        // S tile: rows ty*4+i, key cols tx + 16*j
        float s[4][4] = {};
#pragma unroll
        for (int d = 0; d < 64; d += 4) {
            float4 qv[4], kv[4];
#pragma unroll
            for (int i = 0; i < 4; i++) qv[i] = *(const float4*)&Qs[((ty << 2) + i) * 68 + d];
#pragma unroll
            for (int j = 0; j < 4; j++) kv[j] = *(const float4*)&Ks[(tx + (j << 4)) * 68 + d];
#pragma unroll
            for (int i = 0; i < 4; i++)
#pragma unroll
                for (int j = 0; j < 4; j++)
                    s[i][j] += qv[i].x * kv[j].x + qv[i].y * kv[j].y +
                               qv[i].z * kv[j].z + qv[i].w * kv[j].w;
        }
        // mask + scale (exact reference semantics: masked -> -1e9)
#pragma unroll
        for (int i = 0; i < 4; i++) {
            const float* mrowp = &mask[(size_t)(q0 + (ty << 2) + i) * NKS + k0];
#pragma unroll
            for (int j = 0; j < 4; j++) {
                float mv = __ldg(&mrowp[tx + (j << 4)]);
                s[i][j] = (mv > 0.5f) ? s[i][j] * ATT_SCALE : -1.0e9f;
            }
        }
        // online softmax per row (16-lane butterfly within half-warp)
#pragma unroll
        for (int i = 0; i < 4; i++) {
            float rm = fmaxf(fmaxf(s[i][0], s[i][1]), fmaxf(s[i][2], s[i][3]));
#pragma unroll
            for (int o = 1; o < 16; o <<= 1) rm = fmaxf(rm, __shfl_xor_sync(0xffffffffu, rm, o));
            float mn = fmaxf(mrow[i], rm);
            float corr = __expf(mrow[i] - mn);
            mrow[i] = mn;
            float rs = 0.f;
#pragma unroll
            for (int j = 0; j < 4; j++) {
                float p = __expf(s[i][j] - mn);
                s[i][j] = p;
                rs += p;
            }
#pragma unroll
            for (int o = 1; o < 16; o <<= 1) rs += __shfl_xor_sync(0xffffffffu, rs, o);
            lrow[i] = lrow[i] * corr + rs;
#pragma unroll
            for (int j = 0; j < 4; j++) {
                acc[i][j] *= corr;
                Ps[((ty << 2) + i) * 68 + tx + (j << 4)] = s[i][j];
            }
        }
        __syncthreads();
        // ctx += P @ V  (thread owns d = tx*4..tx*4+3)
#pragma unroll 4
        for (int kk = 0; kk < 64; kk++) {
            float4 vv = *(const float4*)&Vs[kk * 68 + (tx << 2)];
#pragma unroll
            for (int i = 0; i < 4; i++) {
                float p = Ps[((ty << 2) + i) * 68 + kk];
                acc[i][0] += p * vv.x; acc[i][1] += p * vv.y;
                acc[i][2] += p * vv.z; acc[i][3] += p * vv.w;
            }
        }
    }

#pragma unroll
    for (int i = 0; i < 4; i++) {
        float inv = 1.0f / lrow[i];
        float4 o = make_float4(acc[i][0] * inv, acc[i][1] * inv,
                               acc[i][2] * inv, acc[i][3] * inv);
        *(float4*)&ctx[((size_t)(b * NQS + q0 + (ty << 2) + i)) * 256 + h * 64 + (tx << 2)] = o;
    }
}

// ---------------------------------------------------------------------------
// Scatter-add res into persistent update_tensor copy AND output accumulator.
// Duplicate indices within a level require atomics.
// ---------------------------------------------------------------------------
__global__ void scatter_add_kernel(const float* __restrict__ res,
                                   const int* __restrict__ qidx,
                                   float* __restrict__ upd,
                                   float* __restrict__ outp) {
    int row = blockIdx.x;
    int b = row >> 9;          // / NQS
    int i = row & (NQS - 1);
    int t = threadIdx.x;
    int idx = __ldg(&qidx[i]);
    float v = res[(size_t)row * DD + t];
    size_t o = ((size_t)b * NSZ + idx) * DD + t;
    atomicAdd(&upd[o], v);
    atomicAdd(&outp[o], v);
}

// ---------------------------------------------------------------------------
// Host launcher
// ---------------------------------------------------------------------------
extern "C" void kernel_launch(void* const* d_in, const int* in_sizes, int n_in,
                              void* d_out, int out_size) {
    const float* upd_in = (const float*)d_in[0];
    const float* emb    = (const float*)d_in[1];
    const float* maskL  = (const float*)d_in[2];
    const float* Wq     = (const float*)d_in[3];
    const float* Wk     = (const float*)d_in[4];
    const float* Wv     = (const float*)d_in[5];
    const float* Wo     = (const float*)d_in[6];
    const float* W1     = (const float*)d_in[7];
    const float* b1     = (const float*)d_in[8];
    const float* W2     = (const float*)d_in[9];
    const float* b2     = (const float*)d_in[10];
    const float* sys_s  = (const float*)d_in[11];
    const float* sys_b  = (const float*)d_in[12];
    const float* eff_s  = (const float*)d_in[13];
    const float* eff_b  = (const float*)d_in[14];
    const float* in_s   = (const float*)d_in[15];
    const float* in_b   = (const float*)d_in[16];
    const float* out_s  = (const float*)d_in[17];
    const float* out_b  = (const float*)d_in[18];
    const int*   qidx   = (const int*)d_in[19];
    const int*   kidx   = (const int*)d_in[20];
    float* out = (float*)d_out;

    float *p_upd, *p_q, *p_k, *p_Qp, *p_Kp, *p_Vp, *p_ctx, *p_t1, *p_h, *p_gl, *p_f, *p_res;
    cudaGetSymbolAddress((void**)&p_upd, g_upd);
    cudaGetSymbolAddress((void**)&p_q,   g_q);
    cudaGetSymbolAddress((void**)&p_k,   g_k);
    cudaGetSymbolAddress((void**)&p_Qp,  g_Qp);
    cudaGetSymbolAddress((void**)&p_Kp,  g_Kp);
    cudaGetSymbolAddress((void**)&p_Vp,  g_Vp);
    cudaGetSymbolAddress((void**)&p_ctx, g_ctx);
    cudaGetSymbolAddress((void**)&p_t1,  g_t1);
    cudaGetSymbolAddress((void**)&p_h,   g_h);
    cudaGetSymbolAddress((void**)&p_gl,  g_gl);
    cudaGetSymbolAddress((void**)&p_f,   g_f);
    cudaGetSymbolAddress((void**)&p_res, g_res);

    const int ATT_SMEM = 4 * 64 * 68 * (int)sizeof(float);   // 69632
    cudaFuncSetAttribute(attn64_kernel, cudaFuncAttributeMaxDynamicSharedMemorySize, ATT_SMEM);

    const size_t n_upd = (size_t)BB * NSZ * DD;
    copy4_kernel<<<2048, 256>>>(p_upd, upd_in, n_upd / 4);
    zero4_kernel<<<2048, 256>>>(out, n_upd / 4);

    const int MQ = BB * NQS;    // 16384
    const int MK = BB * NKS;    // 32768

    for (int l = 0; l < LLV; l++) {
        const int* qi = qidx + l * NQS;
        const int* ki = kidx + l * NKS;
        const float* mk = maskL + (size_t)l * NQS * NKS;

        gather_ln_kernel<<<MQ, 256>>>(emb, qi, sys_s, sys_b, p_upd, p_q, 9);
        gather_ln_kernel<<<MK, 256>>>(emb, ki, sys_s, sys_b, p_upd, p_k, 10);

        gemm_k256<0><<<dim3(MQ >> 6, 4), 256>>>(p_q, Wq, nullptr, p_Qp);
        gemm_k256<0><<<dim3(MK >> 6, 4), 256>>>(p_k, Wk, nullptr, p_Kp);
        gemm_k256<0><<<dim3(MK >> 6, 4), 256>>>(p_k, Wv, nullptr, p_Vp);

        attn64_kernel<<<dim3(NQS / 64, HH, BB), 256, ATT_SMEM>>>(p_Qp, p_Kp, p_Vp, mk, p_ctx);

        gemm_k256<0><<<dim3(MQ >> 6, 4), 256>>>(p_ctx, Wo, nullptr, p_t1);
        ln_rows_kernel<<<MQ, 256>>>(p_t1, in_s, in_b, p_h);

        gemm_k256<2><<<dim3(MQ >> 6, 4), 256>>>(p_h, W1, b1, p_gl);
        gemm_k256<1><<<dim3(MQ >> 6, 4), 256>>>(p_gl, W2, b2, p_f);

        dln_rows_kernel<<<MQ, 256>>>(p_h, p_f, out_s, out_b, eff_s, eff_b, p_res);

        scatter_add_kernel<<<MQ, 256>>>(p_res, qi, p_upd, out);
    }
}

// round 2
// speedup vs baseline: 1.2828x; 1.2828x over previous
#include <cuda_runtime.h>
#include <cuda_bf16.h>
#include <math.h>
#include <stdint.h>

// Problem constants
#define BB   32
#define NSZ  4096
#define DD   256
#define HH   4
#define DHD  64
#define LLV  6
#define NQS  512
#define NKS  1024
#define ATT_SCALE 0.125f   // 1/sqrt(64)

// ---------------------------------------------------------------------------
// Scratch (device globals; allocation-free rule)
// ---------------------------------------------------------------------------
__device__ float g_upd[(size_t)BB * NSZ * DD];
__device__ float g_q  [(size_t)BB * NQS * DD];
__device__ float g_k  [(size_t)BB * NKS * DD];
__device__ float g_Qp [(size_t)BB * NQS * DD];
__device__ float g_Kp [(size_t)BB * NKS * DD];
__device__ float g_Vp [(size_t)BB * NKS * DD];
__device__ float g_ctx[(size_t)BB * NQS * DD];
__device__ float g_t1 [(size_t)BB * NQS * DD];
__device__ float g_h  [(size_t)BB * NQS * DD];
__device__ float g_gl [(size_t)BB * NQS * DD];
__device__ float g_f  [(size_t)BB * NQS * DD];

// ---------------------------------------------------------------------------
// f32x2 packed-FMA helpers (SASS FFMA2 -- only reachable via PTX fma.rn.f32x2)
// ---------------------------------------------------------------------------
__device__ __forceinline__ unsigned long long dup2f(float x) {
    unsigned long long r;
    asm("mov.b64 %0, {%1, %1};" : "=l"(r) : "f"(x));
    return r;
}
__device__ __forceinline__ void ffma2(unsigned long long& d, unsigned long long a,
                                      unsigned long long b) {
    asm("fma.rn.f32x2 %0, %1, %2, %0;" : "+l"(d) : "l"(a), "l"(b));
}
__device__ __forceinline__ void fmul2(unsigned long long& d, unsigned long long c) {
    asm("mul.rn.f32x2 %0, %0, %1;" : "+l"(d) : "l"(c));
}
__device__ __forceinline__ float2 upk2(unsigned long long u) {
    float2 f;
    asm("mov.b64 {%0, %1}, %2;" : "=f"(f.x), "=f"(f.y) : "l"(u));
    return f;
}

// ---------------------------------------------------------------------------
// init: copy update_tensor into working buffer, zero the output accumulator
// ---------------------------------------------------------------------------
__global__ void init_kernel(float* __restrict__ upd, float* __restrict__ outp,
                            const float* __restrict__ src, size_t n4) {
    size_t i = (size_t)blockIdx.x * blockDim.x + threadIdx.x;
    size_t stride = (size_t)gridDim.x * blockDim.x;
    const float4* s = (const float4*)src;
    float4* u = (float4*)upd;
    float4* o = (float4*)outp;
    float4 z = make_float4(0.f, 0.f, 0.f, 0.f);
    for (; i < n4; i += stride) { u[i] = s[i]; o[i] = z; }
}

// ---------------------------------------------------------------------------
// Warp-per-row helpers: each warp handles one 256-float row, lane owns
// cols lane*4 and 128+lane*4 (two float4s).
// ---------------------------------------------------------------------------
__device__ __forceinline__ float wsum(float v) {
#pragma unroll
    for (int o = 16; o; o >>= 1) v += __shfl_xor_sync(0xffffffffu, v, o);
    return v;
}

// gather + LN: out[row,:] = LN(emb[idx] + upd[b,idx,:]) * s + b
__global__ void gather_ln_w(const float* __restrict__ emb,
                            const int* __restrict__ idxs,
                            const float* __restrict__ scale,
                            const float* __restrict__ bias,
                            const float* __restrict__ upd,
                            float* __restrict__ out, int shift) {
    int w = threadIdx.x >> 5, lane = threadIdx.x & 31;
    int row = (blockIdx.x << 3) + w;
    int b = row >> shift;
    int i = row & ((1 << shift) - 1);
    int idx = __ldg(&idxs[i]);
    const float* e = &emb[(size_t)idx * DD];
    const float* u = &upd[((size_t)b * NSZ + idx) * DD];
    int c0 = lane << 2, c1 = 128 + (lane << 2);
    float4 e0 = *(const float4*)&e[c0], e1 = *(const float4*)&e[c1];
    float4 u0 = *(const float4*)&u[c0], u1 = *(const float4*)&u[c1];
    float x[8] = {e0.x + u0.x, e0.y + u0.y, e0.z + u0.z, e0.w + u0.w,
                  e1.x + u1.x, e1.y + u1.y, e1.z + u1.z, e1.w + u1.w};
    float s = 0.f;
#pragma unroll
    for (int j = 0; j < 8; j++) s += x[j];
    float m = wsum(s) * (1.0f / DD);
    float vs = 0.f;
#pragma unroll
    for (int j = 0; j < 8; j++) { x[j] -= m; vs += x[j] * x[j]; }
    float r = rsqrtf(wsum(vs) * (1.0f / DD) + 1e-5f);
    float4 s0 = *(const float4*)&scale[c0], s1 = *(const float4*)&scale[c1];
    float4 b0 = *(const float4*)&bias[c0],  b1 = *(const float4*)&bias[c1];
    float* o = &out[(size_t)row * DD];
    *(float4*)&o[c0] = make_float4(x[0]*r*s0.x + b0.x, x[1]*r*s0.y + b0.y,
                                   x[2]*r*s0.z + b0.z, x[3]*r*s0.w + b0.w);
    *(float4*)&o[c1] = make_float4(x[4]*r*s1.x + b1.x, x[5]*r*s1.y + b1.y,
                                   x[6]*r*s1.z + b1.z, x[7]*r*s1.w + b1.w);
}

// plain LN over rows
__global__ void ln_rows_w(const float* __restrict__ X,
                          const float* __restrict__ scale,
                          const float* __restrict__ bias,
                          float* __restrict__ out) {
    int w = threadIdx.x >> 5, lane = threadIdx.x & 31;
    size_t row = (size_t)(blockIdx.x << 3) + w;
    int c0 = lane << 2, c1 = 128 + (lane << 2);
    const float* xin = &X[row * DD];
    float4 x0 = *(const float4*)&xin[c0], x1 = *(const float4*)&xin[c1];
    float x[8] = {x0.x, x0.y, x0.z, x0.w, x1.x, x1.y, x1.z, x1.w};
    float s = 0.f;
#pragma unroll
    for (int j = 0; j < 8; j++) s += x[j];
    float m = wsum(s) * (1.0f / DD);
    float vs = 0.f;
#pragma unroll
    for (int j = 0; j < 8; j++) { x[j] -= m; vs += x[j] * x[j]; }
    float r = rsqrtf(wsum(vs) * (1.0f / DD) + 1e-5f);
    float4 s0 = *(const float4*)&scale[c0], s1 = *(const float4*)&scale[c1];
    float4 b0 = *(const float4*)&bias[c0],  b1 = *(const float4*)&bias[c1];
    float* o = &out[row * DD];
    *(float4*)&o[c0] = make_float4(x[0]*r*s0.x + b0.x, x[1]*r*s0.y + b0.y,
                                   x[2]*r*s0.z + b0.z, x[3]*r*s0.w + b0.w);
    *(float4*)&o[c1] = make_float4(x[4]*r*s1.x + b1.x, x[5]*r*s1.y + b1.y,
                                   x[6]*r*s1.z + b1.z, x[7]*r*s1.w + b1.w);
}

// res = LN(LN(Xa+Xb, s1,b1), s2,b2), then atomically scatter-add into upd & out
__global__ void dln_scatter_w(const float* __restrict__ Xa,
                              const float* __restrict__ Xb,
                              const float* __restrict__ s1, const float* __restrict__ bi1,
                              const float* __restrict__ s2, const float* __restrict__ bi2,
                              const int* __restrict__ qidx,
                              float* __restrict__ upd, float* __restrict__ outp) {
    int w = threadIdx.x >> 5, lane = threadIdx.x & 31;
    int row = (blockIdx.x << 3) + w;
    int b = row >> 9;            // / NQS
    int i = row & (NQS - 1);
    int idx = __ldg(&qidx[i]);
    int c0 = lane << 2, c1 = 128 + (lane << 2);
    const float* a = &Xa[(size_t)row * DD];
    const float* f = &Xb[(size_t)row * DD];
    float4 a0 = *(const float4*)&a[c0], a1 = *(const float4*)&a[c1];
    float4 f0 = *(const float4*)&f[c0], f1 = *(const float4*)&f[c1];
    float x[8] = {a0.x + f0.x, a0.y + f0.y, a0.z + f0.z, a0.w + f0.w,
                  a1.x + f1.x, a1.y + f1.y, a1.z + f1.z, a1.w + f1.w};
    float s = 0.f;
#pragma unroll
    for (int j = 0; j < 8; j++) s += x[j];
    float m = wsum(s) * (1.0f / DD);
    float vs = 0.f;
#pragma unroll
    for (int j = 0; j < 8; j++) { x[j] -= m; vs += x[j] * x[j]; }
    float r = rsqrtf(wsum(vs) * (1.0f / DD) + 1e-5f);
    float4 g0 = *(const float4*)&s1[c0], g1 = *(const float4*)&s1[c1];
    float4 h0 = *(const float4*)&bi1[c0], h1 = *(const float4*)&bi1[c1];
    float gg[8] = {g0.x, g0.y, g0.z, g0.w, g1.x, g1.y, g1.z, g1.w};
    float hh[8] = {h0.x, h0.y, h0.z, h0.w, h1.x, h1.y, h1.z, h1.w};
#pragma unroll
    for (int j = 0; j < 8; j++) x[j] = x[j] * r * gg[j] + hh[j];
    // second LN
    s = 0.f;
#pragma unroll
    for (int j = 0; j < 8; j++) s += x[j];
    m = wsum(s) * (1.0f / DD);
    vs = 0.f;
#pragma unroll
    for (int j = 0; j < 8; j++) { x[j] -= m; vs += x[j] * x[j]; }
    r = rsqrtf(wsum(vs) * (1.0f / DD) + 1e-5f);
    g0 = *(const float4*)&s2[c0]; g1 = *(const float4*)&s2[c1];
    h0 = *(const float4*)&bi2[c0]; h1 = *(const float4*)&bi2[c1];
    float g2[8] = {g0.x, g0.y, g0.z, g0.w, g1.x, g1.y, g1.z, g1.w};
    float h2[8] = {h0.x, h0.y, h0.z, h0.w, h1.x, h1.y, h1.z, h1.w};
    size_t base = ((size_t)b * NSZ + idx) * DD;
#pragma unroll
    for (int j = 0; j < 8; j++) {
        float v = x[j] * r * g2[j] + h2[j];
        int c = (j < 4) ? c0 + j : c1 + (j - 4);
        atomicAdd(&upd[base + c], v);
        atomicAdd(&outp[base + c], v);
    }
}

// ---------------------------------------------------------------------------
// GEMM via FFMA2: C[M,256] = A[M,256] @ W[256,256] (+bias)(+gelu)
// BM=128, BN=128, BK=16, 256 threads. Thread tile: 8m (4 pairs) x 8n.
// m groups: ty*4 and 64+ty*4; n groups: tx*4 and 64+tx*4.
// EPI: 0 = none, 1 = +bias, 2 = +bias then tanh-gelu
// ---------------------------------------------------------------------------
__device__ __forceinline__ float gelu_tanh(float x) {
    float x3 = x * x * x;
    return 0.5f * x * (1.0f + tanhf(0.7978845608028654f * (x + 0.044715f * x3)));
}

template <int EPI>
__global__ void __launch_bounds__(256, 1)
gemm2_k256(const float* __restrict__ A,
           const float* __restrict__ W,
           const float* __restrict__ bias,
           float* __restrict__ C) {
    __shared__ __align__(16) float As[16][132];   // [k][m]
    __shared__ __align__(16) float Bs[16][132];   // [k][n]
    const int bm = blockIdx.x << 7;
    const int bn = blockIdx.y << 7;
    const int t = threadIdx.x;
    const int tx = t & 15, ty = t >> 4;

    unsigned long long acc[4][8];
#pragma unroll
    for (int p = 0; p < 4; p++)
#pragma unroll
        for (int j = 0; j < 8; j++) acc[p][j] = 0ULL;

    for (int k0 = 0; k0 < 256; k0 += 16) {
        // A tile: 128m x 16k = 512 float4, transposed store
#pragma unroll
        for (int r = 0; r < 2; r++) {
            int id = t + (r << 8);
            int m = id >> 2, kq = (id & 3) << 2;
            float4 v = *(const float4*)&A[(size_t)(bm + m) * 256 + k0 + kq];
            As[kq + 0][m] = v.x; As[kq + 1][m] = v.y;
            As[kq + 2][m] = v.z; As[kq + 3][m] = v.w;
        }
        // B tile: 16k x 128n = 512 float4, natural store
#pragma unroll
        for (int r = 0; r < 2; r++) {
            int id = t + (r << 8);
            int kk = id >> 5, nq = (id & 31) << 2;
            *(float4*)&Bs[kk][nq] = *(const float4*)&W[(size_t)(k0 + kk) * 256 + bn + nq];
        }
        __syncthreads();
#pragma unroll
        for (int kk = 0; kk < 16; kk++) {
            ulonglong2 a0 = *(const ulonglong2*)&As[kk][ty << 2];
            ulonglong2 a1 = *(const ulonglong2*)&As[kk][64 + (ty << 2)];
            float4 b0 = *(const float4*)&Bs[kk][tx << 2];
            float4 b1 = *(const float4*)&Bs[kk][64 + (tx << 2)];
            unsigned long long bd[8] = {dup2f(b0.x), dup2f(b0.y), dup2f(b0.z), dup2f(b0.w),
                                        dup2f(b1.x), dup2f(b1.y), dup2f(b1.z), dup2f(b1.w)};
            unsigned long long ap[4] = {a0.x, a0.y, a1.x, a1.y};
#pragma unroll
            for (int p = 0; p < 4; p++)
#pragma unroll
                for (int j = 0; j < 8; j++) ffma2(acc[p][j], ap[p], bd[j]);
        }
        __syncthreads();
    }

    // epilogue
    float4 bz0 = make_float4(0.f, 0.f, 0.f, 0.f), bz1 = bz0;
    if (EPI >= 1) {
        bz0 = *(const float4*)&bias[bn + (tx << 2)];
        bz1 = *(const float4*)&bias[bn + 64 + (tx << 2)];
    }
#pragma unroll
    for (int p = 0; p < 4; p++) {
        int m0 = (p < 2) ? (ty << 2) + (p << 1) : 64 + (ty << 2) + ((p - 2) << 1);
#pragma unroll
        for (int hf = 0; hf < 2; hf++) {
            float c[8];
#pragma unroll
            for (int j = 0; j < 8; j++) {
                float2 f = upk2(acc[p][j]);
                c[j] = hf ? f.y : f.x;
            }
            float4 o0 = make_float4(c[0] + bz0.x, c[1] + bz0.y, c[2] + bz0.z, c[3] + bz0.w);
            float4 o1 = make_float4(c[4] + bz1.x, c[5] + bz1.y, c[6] + bz1.z, c[7] + bz1.w);
            if (EPI == 2) {
                o0.x = gelu_tanh(o0.x); o0.y = gelu_tanh(o0.y);
                o0.z = gelu_tanh(o0.z); o0.w = gelu_tanh(o0.w);
                o1.x = gelu_tanh(o1.x); o1.y = gelu_tanh(o1.y);
                o1.z = gelu_tanh(o1.z); o1.w = gelu_tanh(o1.w);
            }
            size_t rowoff = (size_t)(bm + m0 + hf) * 256;
            *(float4*)&C[rowoff + bn + (tx << 2)] = o0;
            *(float4*)&C[rowoff + bn + 64 + (tx << 2)] = o1;
        }
    }
}

// ---------------------------------------------------------------------------
// Flash attention via FFMA2. Grid: (NQ/128, H, B), 256 threads.
// Q tile 128, K/V chunks of 64, head dim 64.
// Thread tile S: 8q (4 pairs; rows ty*4.. and 64+ty*4..) x 4k (tx*4..).
// Thread tile PV: same 8q rows x 4dh (2 pairs; cols tx*4..).
// ---------------------------------------------------------------------------
__global__ void __launch_bounds__(256, 1)
attn128(const float* __restrict__ Qm,
        const float* __restrict__ Km,
        const float* __restrict__ Vm,
        const float* __restrict__ mask,
        float* __restrict__ ctx) {
    extern __shared__ float sm[];
    float* Qs = sm;                 // [64][132]  (d-major, q cols)
    float* Ks = Qs + 64 * 132;      // [64][68]   (d-major, k cols)
    float* Vs = Ks + 64 * 68;       // [64][68]   (k-major, d cols)
    float* Ps = Vs + 64 * 68;       // [128][68]  (q-major, k cols)

    const int t = threadIdx.x;
    const int tx = t & 15, ty = t >> 4;
    const int b = blockIdx.z, h = blockIdx.y, q0 = blockIdx.x << 7;

    // load Q tile transposed: Qs[d][q]
#pragma unroll
    for (int r = 0; r < 8; r++) {
        int id = t + (r << 8);
        int q = id >> 4, dq = (id & 15) << 2;
        float4 v = *(const float4*)&Qm[((size_t)(b * NQS + q0 + q)) * 256 + h * 64 + dq];
        Qs[(dq + 0) * 132 + q] = v.x; Qs[(dq + 1) * 132 + q] = v.y;
        Qs[(dq + 2) * 132 + q] = v.z; Qs[(dq + 3) * 132 + q] = v.w;
    }

    float mrow[8], lrow[8];
    unsigned long long cacc[8][2];
#pragma unroll
    for (int i = 0; i < 8; i++) {
        mrow[i] = -3.0e38f; lrow[i] = 0.f;
        cacc[i][0] = 0ULL; cacc[i][1] = 0ULL;
    }

#pragma unroll 1
    for (int k0 = 0; k0 < NKS; k0 += 64) {
        __syncthreads();
        // load K (transposed) and V (natural) chunk
#pragma unroll
        for (int r = 0; r < 4; r++) {
            int id = t + (r << 8);
            int kk = id >> 4, dq = (id & 15) << 2;
            size_t off = ((size_t)(b * NKS + k0 + kk)) * 256 + h * 64 + dq;
            float4 kv = *(const float4*)&Km[off];
            Ks[(dq + 0) * 68 + kk] = kv.x; Ks[(dq + 1) * 68 + kk] = kv.y;
            Ks[(dq + 2) * 68 + kk] = kv.z; Ks[(dq + 3) * 68 + kk] = kv.w;
            *(float4*)&Vs[kk * 68 + dq] = *(const float4*)&Vm[off];
        }
        __syncthreads();

        // S = Q K^T over d
        unsigned long long s2[4][4];
#pragma unroll
        for (int p = 0; p < 4; p++)
#pragma unroll
            for (int j = 0; j < 4; j++) s2[p][j] = 0ULL;
#pragma unroll 16
        for (int d = 0; d < 64; d++) {
            ulonglong2 qa = *(const ulonglong2*)&Qs[d * 132 + (ty << 2)];
            ulonglong2 qb = *(const ulonglong2*)&Qs[d * 132 + 64 + (ty << 2)];
            float4 kv = *(const float4*)&Ks[d * 68 + (tx << 2)];
            unsigned long long kd[4] = {dup2f(kv.x), dup2f(kv.y), dup2f(kv.z), dup2f(kv.w)};
            unsigned long long qp[4] = {qa.x, qa.y, qb.x, qb.y};
#pragma unroll
            for (int p = 0; p < 4; p++)
#pragma unroll
                for (int j = 0; j < 4; j++) ffma2(s2[p][j], qp[p], kd[j]);
        }

        // unpack, mask, online softmax, store P, rescale ctx acc
#pragma unroll
        for (int i = 0; i < 8; i++) {
            int rq = (i < 4) ? (ty << 2) + i : 64 + (ty << 2) + (i - 4);
            float sf[4];
#pragma unroll
            for (int j = 0; j < 4; j++) {
                float2 f = upk2(s2[i >> 1][j]);
                sf[j] = (i & 1) ? f.y : f.x;
            }
            float4 mv = *(const float4*)&mask[(size_t)(q0 + rq) * NKS + k0 + (tx << 2)];
            sf[0] = (mv.x > 0.5f) ? sf[0] * ATT_SCALE : -1.0e9f;
            sf[1] = (mv.y > 0.5f) ? sf[1] * ATT_SCALE : -1.0e9f;
            sf[2] = (mv.z > 0.5f) ? sf[2] * ATT_SCALE : -1.0e9f;
            sf[3] = (mv.w > 0.5f) ? sf[3] * ATT_SCALE : -1.0e9f;
            float rm = fmaxf(fmaxf(sf[0], sf[1]), fmaxf(sf[2], sf[3]));
#pragma unroll
            for (int o = 1; o < 16; o <<= 1) rm = fmaxf(rm, __shfl_xor_sync(0xffffffffu, rm, o));
            float mn = fmaxf(mrow[i], rm);
            float corr = __expf(mrow[i] - mn);
            mrow[i] = mn;
            float rs = 0.f;
#pragma unroll
            for (int j = 0; j < 4; j++) {
                float p = __expf(sf[j] - mn);
                sf[j] = p;
                rs += p;
            }
#pragma unroll
            for (int o = 1; o < 16; o <<= 1) rs += __shfl_xor_sync(0xffffffffu, rs, o);
            lrow[i] = lrow[i] * corr + rs;
            unsigned long long cd = dup2f(corr);
            fmul2(cacc[i][0], cd);
            fmul2(cacc[i][1], cd);
            *(float4*)&Ps[rq * 68 + (tx << 2)] = make_float4(sf[0], sf[1], sf[2], sf[3]);
        }
        __syncwarp();   // P rows are produced & consumed within one warp

        // ctx += P @ V
#pragma unroll 2
        for (int kk = 0; kk < 64; kk += 4) {
            float pk[8][4];
#pragma unroll
            for (int i = 0; i < 8; i++) {
                int rq = (i < 4) ? (ty << 2) + i : 64 + (ty << 2) + (i - 4);
                float4 p4 = *(const float4*)&Ps[rq * 68 + kk];
                pk[i][0] = p4.x; pk[i][1] = p4.y; pk[i][2] = p4.z; pk[i][3] = p4.w;
            }
#pragma unroll
            for (int u = 0; u < 4; u++) {
                ulonglong2 vv = *(const ulonglong2*)&Vs[(kk + u) * 68 + (tx << 2)];
#pragma unroll
                for (int i = 0; i < 8; i++) {
                    unsigned long long pd = dup2f(pk[i][u]);
                    ffma2(cacc[i][0], pd, vv.x);
                    ffma2(cacc[i][1], pd, vv.y);
                }
            }
        }
    }

    // normalize and write ctx
#pragma unroll
    for (int i = 0; i < 8; i++) {
        int rq = (i < 4) ? (ty << 2) + i : 64 + (ty << 2) + (i - 4);
        float inv = 1.0f / lrow[i];
        float2 u0 = upk2(cacc[i][0]);
        float2 u1 = upk2(cacc[i][1]);
        float4 o = make_float4(u0.x * inv, u0.y * inv, u1.x * inv, u1.y * inv);
        *(float4*)&ctx[((size_t)(b * NQS + q0 + rq)) * 256 + h * 64 + (tx << 2)] = o;
    }
}

// ---------------------------------------------------------------------------
// Host launcher
// ---------------------------------------------------------------------------
extern "C" void kernel_launch(void* const* d_in, const int* in_sizes, int n_in,
                              void* d_out, int out_size) {
    const float* upd_in = (const float*)d_in[0];
    const float* emb    = (const float*)d_in[1];
    const float* maskL  = (const float*)d_in[2];
    const float* Wq     = (const float*)d_in[3];
    const float* Wk     = (const float*)d_in[4];
    const float* Wv     = (const float*)d_in[5];
    const float* Wo     = (const float*)d_in[6];
    const float* W1     = (const float*)d_in[7];
    const float* b1     = (const float*)d_in[8];
    const float* W2     = (const float*)d_in[9];
    const float* b2     = (const float*)d_in[10];
    const float* sys_s  = (const float*)d_in[11];
    const float* sys_b  = (const float*)d_in[12];
    const float* eff_s  = (const float*)d_in[13];
    const float* eff_b  = (const float*)d_in[14];
    const float* in_s   = (const float*)d_in[15];
    const float* in_b   = (const float*)d_in[16];
    const float* out_s  = (const float*)d_in[17];
    const float* out_b  = (const float*)d_in[18];
    const int*   qidx   = (const int*)d_in[19];
    const int*   kidx   = (const int*)d_in[20];
    float* out = (float*)d_out;

    float *p_upd, *p_q, *p_k, *p_Qp, *p_Kp, *p_Vp, *p_ctx, *p_t1, *p_h, *p_gl, *p_f;
    cudaGetSymbolAddress((void**)&p_upd, g_upd);
    cudaGetSymbolAddress((void**)&p_q,   g_q);
    cudaGetSymbolAddress((void**)&p_k,   g_k);
    cudaGetSymbolAddress((void**)&p_Qp,  g_Qp);
    cudaGetSymbolAddress((void**)&p_Kp,  g_Kp);
    cudaGetSymbolAddress((void**)&p_Vp,  g_Vp);
    cudaGetSymbolAddress((void**)&p_ctx, g_ctx);
    cudaGetSymbolAddress((void**)&p_t1,  g_t1);
    cudaGetSymbolAddress((void**)&p_h,   g_h);
    cudaGetSymbolAddress((void**)&p_gl,  g_gl);
    cudaGetSymbolAddress((void**)&p_f,   g_f);

    const int ATT_SMEM = (64*132 + 64*68 + 64*68 + 128*68) * (int)sizeof(float); // 103424
    cudaFuncSetAttribute(attn128, cudaFuncAttributeMaxDynamicSharedMemorySize, ATT_SMEM);

    const size_t n_upd = (size_t)BB * NSZ * DD;
    init_kernel<<<2048, 256>>>(p_upd, out, upd_in, n_upd / 4);

    const int MQ = BB * NQS;    // 16384
    const int MK = BB * NKS;    // 32768

    for (int l = 0; l < LLV; l++) {
        const int* qi = qidx + l * NQS;
        const int* ki = kidx + l * NKS;
        const float* mk = maskL + (size_t)l * NQS * NKS;

        gather_ln_w<<<MQ / 8, 256>>>(emb, qi, sys_s, sys_b, p_upd, p_q, 9);
        gather_ln_w<<<MK / 8, 256>>>(emb, ki, sys_s, sys_b, p_upd, p_k, 10);

        gemm2_k256<0><<<dim3(MQ >> 7, 2), 256>>>(p_q, Wq, nullptr, p_Qp);
        gemm2_k256<0><<<dim3(MK >> 7, 2), 256>>>(p_k, Wk, nullptr, p_Kp);
        gemm2_k256<0><<<dim3(MK >> 7, 2), 256>>>(p_k, Wv, nullptr, p_Vp);

        attn128<<<dim3(NQS / 128, HH, BB), 256, ATT_SMEM>>>(p_Qp, p_Kp, p_Vp, mk, p_ctx);

        gemm2_k256<0><<<dim3(MQ >> 7, 2), 256>>>(p_ctx, Wo, nullptr, p_t1);
        ln_rows_w<<<MQ / 8, 256>>>(p_t1, in_s, in_b, p_h);

        gemm2_k256<2><<<dim3(MQ >> 7, 2), 256>>>(p_h, W1, b1, p_gl);
        gemm2_k256<1><<<dim3(MQ >> 7, 2), 256>>>(p_gl, W2, b2, p_f);

        dln_scatter_w<<<MQ / 8, 256>>>(p_h, p_f, out_s, out_b, eff_s, eff_b,
                                       qi, p_upd, out);
    }
}

// round 3
// speedup vs baseline: 1.4879x; 1.1599x over previous
#include <cuda_runtime.h>
#include <cuda_bf16.h>
#include <math.h>
#include <stdint.h>

// Problem constants
#define BB   32
#define NSZ  4096
#define DD   256
#define HH   4
#define DHD  64
#define LLV  6
#define NQS  512
#define NKS  1024
#define ATT_SCALE 0.125f   // 1/sqrt(64)

// ---------------------------------------------------------------------------
// Scratch (device globals; allocation-free rule)
// ---------------------------------------------------------------------------
__device__ float g_upd[(size_t)BB * NSZ * DD];
__device__ float g_q  [(size_t)BB * NQS * DD];
__device__ float g_k  [(size_t)BB * NKS * DD];
__device__ float g_Qp [(size_t)BB * NQS * DD];
__device__ float g_Kp [(size_t)BB * NKS * DD];
__device__ float g_Vp [(size_t)BB * NKS * DD];
__device__ float g_ctx[(size_t)BB * NQS * DD];
__device__ float g_t1 [(size_t)BB * NQS * DD];
__device__ float g_h  [(size_t)BB * NQS * DD];
__device__ float g_gl [(size_t)BB * NQS * DD];
__device__ float g_f  [(size_t)BB * NQS * DD];
__device__ unsigned g_mb[NQS * NKS / 32];       // bit-packed mask for current level

// ---------------------------------------------------------------------------
// f32x2 packed-FMA helpers (SASS FFMA2 -- only reachable via PTX fma.rn.f32x2)
// ---------------------------------------------------------------------------
__device__ __forceinline__ unsigned long long dup2f(float x) {
    unsigned long long r;
    asm("mov.b64 %0, {%1, %1};" : "=l"(r) : "f"(x));
    return r;
}
__device__ __forceinline__ void ffma2(unsigned long long& d, unsigned long long a,
                                      unsigned long long b) {
    asm("fma.rn.f32x2 %0, %1, %2, %0;" : "+l"(d) : "l"(a), "l"(b));
}
__device__ __forceinline__ void fmul2(unsigned long long& d, unsigned long long c) {
    asm("mul.rn.f32x2 %0, %0, %1;" : "+l"(d) : "l"(c));
}
__device__ __forceinline__ float2 upk2(unsigned long long u) {
    float2 f;
    asm("mov.b64 {%0, %1}, %2;" : "=f"(f.x), "=f"(f.y) : "l"(u));
    return f;
}

// cp.async helpers
__device__ __forceinline__ void cp16(float* s, const float* g) {
    unsigned sa = (unsigned)__cvta_generic_to_shared(s);
    asm volatile("cp.async.cg.shared.global [%0], [%1], 16;" :: "r"(sa), "l"(g));
}
__device__ __forceinline__ void cp_commit() {
    asm volatile("cp.async.commit_group;" ::: "memory");
}
__device__ __forceinline__ void cp_waitall() {
    asm volatile("cp.async.wait_group 0;" ::: "memory");
}

// ---------------------------------------------------------------------------
// init: copy update_tensor into working buffer, zero the output accumulator
// ---------------------------------------------------------------------------
__global__ void init_kernel(float* __restrict__ upd, float* __restrict__ outp,
                            const float* __restrict__ src, size_t n4) {
    size_t i = (size_t)blockIdx.x * blockDim.x + threadIdx.x;
    size_t stride = (size_t)gridDim.x * blockDim.x;
    const float4* s = (const float4*)src;
    float4* u = (float4*)upd;
    float4* o = (float4*)outp;
    float4 z = make_float4(0.f, 0.f, 0.f, 0.f);
    for (; i < n4; i += stride) { u[i] = s[i]; o[i] = z; }
}

// bit-pack mask (one thread per 32 mask entries)
__global__ void pack_mask_kernel(const float* __restrict__ mask, unsigned* __restrict__ mb) {
    int i = blockIdx.x * blockDim.x + threadIdx.x;
    const float4* m = (const float4*)&mask[(size_t)i * 32];
    unsigned v = 0;
#pragma unroll
    for (int j = 0; j < 8; j++) {
        float4 f = m[j];
        v |= (f.x > 0.5f ? 1u : 0u) << (j * 4 + 0);
        v |= (f.y > 0.5f ? 1u : 0u) << (j * 4 + 1);
        v |= (f.z > 0.5f ? 1u : 0u) << (j * 4 + 2);
        v |= (f.w > 0.5f ? 1u : 0u) << (j * 4 + 3);
    }
    mb[i] = v;
}

// ---------------------------------------------------------------------------
// Warp-per-row elementwise helpers
// ---------------------------------------------------------------------------
__device__ __forceinline__ float wsum(float v) {
#pragma unroll
    for (int o = 16; o; o >>= 1) v += __shfl_xor_sync(0xffffffffu, v, o);
    return v;
}

__global__ void gather_ln_w(const float* __restrict__ emb,
                            const int* __restrict__ idxs,
                            const float* __restrict__ scale,
                            const float* __restrict__ bias,
                            const float* __restrict__ upd,
                            float* __restrict__ out, int shift) {
    int w = threadIdx.x >> 5, lane = threadIdx.x & 31;
    int row = (blockIdx.x << 3) + w;
    int b = row >> shift;
    int i = row & ((1 << shift) - 1);
    int idx = __ldg(&idxs[i]);
    const float* e = &emb[(size_t)idx * DD];
    const float* u = &upd[((size_t)b * NSZ + idx) * DD];
    int c0 = lane << 2, c1 = 128 + (lane << 2);
    float4 e0 = *(const float4*)&e[c0], e1 = *(const float4*)&e[c1];
    float4 u0 = *(const float4*)&u[c0], u1 = *(const float4*)&u[c1];
    float x[8] = {e0.x + u0.x, e0.y + u0.y, e0.z + u0.z, e0.w + u0.w,
                  e1.x + u1.x, e1.y + u1.y, e1.z + u1.z, e1.w + u1.w};
    float s = 0.f;
#pragma unroll
    for (int j = 0; j < 8; j++) s += x[j];
    float m = wsum(s) * (1.0f / DD);
    float vs = 0.f;
#pragma unroll
    for (int j = 0; j < 8; j++) { x[j] -= m; vs += x[j] * x[j]; }
    float r = rsqrtf(wsum(vs) * (1.0f / DD) + 1e-5f);
    float4 s0 = *(const float4*)&scale[c0], s1 = *(const float4*)&scale[c1];
    float4 b0 = *(const float4*)&bias[c0],  b1 = *(const float4*)&bias[c1];
    float* o = &out[(size_t)row * DD];
    *(float4*)&o[c0] = make_float4(x[0]*r*s0.x + b0.x, x[1]*r*s0.y + b0.y,
                                   x[2]*r*s0.z + b0.z, x[3]*r*s0.w + b0.w);
    *(float4*)&o[c1] = make_float4(x[4]*r*s1.x + b1.x, x[5]*r*s1.y + b1.y,
                                   x[6]*r*s1.z + b1.z, x[7]*r*s1.w + b1.w);
}

__global__ void ln_rows_w(const float* __restrict__ X,
                          const float* __restrict__ scale,
                          const float* __restrict__ bias,
                          float* __restrict__ out) {
    int w = threadIdx.x >> 5, lane = threadIdx.x & 31;
    size_t row = (size_t)(blockIdx.x << 3) + w;
    int c0 = lane << 2, c1 = 128 + (lane << 2);
    const float* xin = &X[row * DD];
    float4 x0 = *(const float4*)&xin[c0], x1 = *(const float4*)&xin[c1];
    float x[8] = {x0.x, x0.y, x0.z, x0.w, x1.x, x1.y, x1.z, x1.w};
    float s = 0.f;
#pragma unroll
    for (int j = 0; j < 8; j++) s += x[j];
    float m = wsum(s) * (1.0f / DD);
    float vs = 0.f;
#pragma unroll
    for (int j = 0; j < 8; j++) { x[j] -= m; vs += x[j] * x[j]; }
    float r = rsqrtf(wsum(vs) * (1.0f / DD) + 1e-5f);
    float4 s0 = *(const float4*)&scale[c0], s1 = *(const float4*)&scale[c1];
    float4 b0 = *(const float4*)&bias[c0],  b1 = *(const float4*)&bias[c1];
    float* o = &out[row * DD];
    *(float4*)&o[c0] = make_float4(x[0]*r*s0.x + b0.x, x[1]*r*s0.y + b0.y,
                                   x[2]*r*s0.z + b0.z, x[3]*r*s0.w + b0.w);
    *(float4*)&o[c1] = make_float4(x[4]*r*s1.x + b1.x, x[5]*r*s1.y + b1.y,
                                   x[6]*r*s1.z + b1.z, x[7]*r*s1.w + b1.w);
}

__global__ void dln_scatter_w(const float* __restrict__ Xa,
                              const float* __restrict__ Xb,
                              const float* __restrict__ s1, const float* __restrict__ bi1,
                              const float* __restrict__ s2, const float* __restrict__ bi2,
                              const int* __restrict__ qidx,
                              float* __restrict__ upd, float* __restrict__ outp) {
    int w = threadIdx.x >> 5, lane = threadIdx.x & 31;
    int row = (blockIdx.x << 3) + w;
    int b = row >> 9;
    int i = row & (NQS - 1);
    int idx = __ldg(&qidx[i]);
    int c0 = lane << 2, c1 = 128 + (lane << 2);
    const float* a = &Xa[(size_t)row * DD];
    const float* f = &Xb[(size_t)row * DD];
    float4 a0 = *(const float4*)&a[c0], a1 = *(const float4*)&a[c1];
    float4 f0 = *(const float4*)&f[c0], f1 = *(const float4*)&f[c1];
    float x[8] = {a0.x + f0.x, a0.y + f0.y, a0.z + f0.z, a0.w + f0.w,
                  a1.x + f1.x, a1.y + f1.y, a1.z + f1.z, a1.w + f1.w};
    float s = 0.f;
#pragma unroll
    for (int j = 0; j < 8; j++) s += x[j];
    float m = wsum(s) * (1.0f / DD);
    float vs = 0.f;
#pragma unroll
    for (int j = 0; j < 8; j++) { x[j] -= m; vs += x[j] * x[j]; }
    float r = rsqrtf(wsum(vs) * (1.0f / DD) + 1e-5f);
    float4 g0 = *(const float4*)&s1[c0], g1 = *(const float4*)&s1[c1];
    float4 h0 = *(const float4*)&bi1[c0], h1 = *(const float4*)&bi1[c1];
    float gg[8] = {g0.x, g0.y, g0.z, g0.w, g1.x, g1.y, g1.z, g1.w};
    float hh[8] = {h0.x, h0.y, h0.z, h0.w, h1.x, h1.y, h1.z, h1.w};
#pragma unroll
    for (int j = 0; j < 8; j++) x[j] = x[j] * r * gg[j] + hh[j];
    s = 0.f;
#pragma unroll
    for (int j = 0; j < 8; j++) s += x[j];
    m = wsum(s) * (1.0f / DD);
    vs = 0.f;
#pragma unroll
    for (int j = 0; j < 8; j++) { x[j] -= m; vs += x[j] * x[j]; }
    r = rsqrtf(wsum(vs) * (1.0f / DD) + 1e-5f);
    g0 = *(const float4*)&s2[c0]; g1 = *(const float4*)&s2[c1];
    h0 = *(const float4*)&bi2[c0]; h1 = *(const float4*)&bi2[c1];
    float g2[8] = {g0.x, g0.y, g0.z, g0.w, g1.x, g1.y, g1.z, g1.w};
    float h2[8] = {h0.x, h0.y, h0.z, h0.w, h1.x, h1.y, h1.z, h1.w};
    size_t base = ((size_t)b * NSZ + idx) * DD;
#pragma unroll
    for (int j = 0; j < 8; j++) {
        float v = x[j] * r * g2[j] + h2[j];
        int c = (j < 4) ? c0 + j : c1 + (j - 4);
        atomicAdd(&upd[base + c], v);
        atomicAdd(&outp[base + c], v);
    }
}

// ---------------------------------------------------------------------------
// GEMM via FFMA2, BK=32, double-buffered (cp.async B, reg-staged A).
// BM=BN=128, 256 threads, thread tile 8m(4 pairs) x 8n.
// EPI: 0 none, 1 +bias, 2 +bias+gelu
// ---------------------------------------------------------------------------
__device__ __forceinline__ float gelu_tanh(float x) {
    float x3 = x * x * x;
    return 0.5f * x * (1.0f + tanhf(0.7978845608028654f * (x + 0.044715f * x3)));
}

#define GEMM_SMEM (4 * 32 * 132 * (int)sizeof(float))   // 2 A bufs + 2 B bufs = 67584

template <int EPI>
__global__ void __launch_bounds__(256, 2)
gemm2_db(const float* __restrict__ A,
         const float* __restrict__ W,
         const float* __restrict__ bias,
         float* __restrict__ C) {
    extern __shared__ float smg[];
    float* As = smg;               // [2][32][132]
    float* Bs = smg + 2 * 32 * 132;
    const int bm = blockIdx.x << 7;
    const int bn = blockIdx.y << 7;
    const int t = threadIdx.x;
    const int tx = t & 15, ty = t >> 4;

    unsigned long long acc[4][8] = {};
    float4 areg[4];

    // prologue: tile 0
#pragma unroll
    for (int r = 0; r < 4; r++) {
        int id = t + (r << 8);
        int m = id >> 3, kq = (id & 7) << 2;
        areg[r] = *(const float4*)&A[(size_t)(bm + m) * 256 + kq];
    }
#pragma unroll
    for (int r = 0; r < 4; r++) {
        int id = t + (r << 8);
        int kk = id >> 5, nq = (id & 31) << 2;
        cp16(&Bs[kk * 132 + nq], &W[(size_t)kk * 256 + bn + nq]);
    }
    cp_commit();
#pragma unroll
    for (int r = 0; r < 4; r++) {
        int id = t + (r << 8);
        int m = id >> 3, kq = (id & 7) << 2;
        As[(kq + 0) * 132 + m] = areg[r].x;
        As[(kq + 1) * 132 + m] = areg[r].y;
        As[(kq + 2) * 132 + m] = areg[r].z;
        As[(kq + 3) * 132 + m] = areg[r].w;
    }
    cp_waitall();
    __syncthreads();

    int cur = 0;
#pragma unroll 1
    for (int kt = 0; kt < 8; kt++) {
        const int k0n = (kt + 1) << 5;
        if (kt < 7) {
#pragma unroll
            for (int r = 0; r < 4; r++) {
                int id = t + (r << 8);
                int m = id >> 3, kq = (id & 7) << 2;
                areg[r] = *(const float4*)&A[(size_t)(bm + m) * 256 + k0n + kq];
            }
            float* Bn = Bs + (cur ^ 1) * 4224;
#pragma unroll
            for (int r = 0; r < 4; r++) {
                int id = t + (r << 8);
                int kk = id >> 5, nq = (id & 31) << 2;
                cp16(&Bn[kk * 132 + nq], &W[(size_t)(k0n + kk) * 256 + bn + nq]);
            }
            cp_commit();
        }
        const float* Ac = As + cur * 4224;
        const float* Bc = Bs + cur * 4224;
#pragma unroll
        for (int kk = 0; kk < 32; kk++) {
            ulonglong2 a0 = *(const ulonglong2*)&Ac[kk * 132 + (ty << 2)];
            ulonglong2 a1 = *(const ulonglong2*)&Ac[kk * 132 + 64 + (ty << 2)];
            float4 b0 = *(const float4*)&Bc[kk * 132 + (tx << 2)];
            float4 b1 = *(const float4*)&Bc[kk * 132 + 64 + (tx << 2)];
            unsigned long long bd[8] = {dup2f(b0.x), dup2f(b0.y), dup2f(b0.z), dup2f(b0.w),
                                        dup2f(b1.x), dup2f(b1.y), dup2f(b1.z), dup2f(b1.w)};
            unsigned long long ap[4] = {a0.x, a0.y, a1.x, a1.y};
#pragma unroll
            for (int p = 0; p < 4; p++)
#pragma unroll
                for (int j = 0; j < 8; j++) ffma2(acc[p][j], ap[p], bd[j]);
        }
        if (kt < 7) {
            float* An = As + (cur ^ 1) * 4224;
#pragma unroll
            for (int r = 0; r < 4; r++) {
                int id = t + (r << 8);
                int m = id >> 3, kq = (id & 7) << 2;
                An[(kq + 0) * 132 + m] = areg[r].x;
                An[(kq + 1) * 132 + m] = areg[r].y;
                An[(kq + 2) * 132 + m] = areg[r].z;
                An[(kq + 3) * 132 + m] = areg[r].w;
            }
            cp_waitall();
            __syncthreads();
            cur ^= 1;
        }
    }

    // epilogue
    float4 bz0 = make_float4(0.f, 0.f, 0.f, 0.f), bz1 = bz0;
    if (EPI >= 1) {
        bz0 = *(const float4*)&bias[bn + (tx << 2)];
        bz1 = *(const float4*)&bias[bn + 64 + (tx << 2)];
    }
#pragma unroll
    for (int p = 0; p < 4; p++) {
        int m0 = (p < 2) ? (ty << 2) + (p << 1) : 64 + (ty << 2) + ((p - 2) << 1);
#pragma unroll
        for (int hf = 0; hf < 2; hf++) {
            float c[8];
#pragma unroll
            for (int j = 0; j < 8; j++) {
                float2 f = upk2(acc[p][j]);
                c[j] = hf ? f.y : f.x;
            }
            float4 o0 = make_float4(c[0] + bz0.x, c[1] + bz0.y, c[2] + bz0.z, c[3] + bz0.w);
            float4 o1 = make_float4(c[4] + bz1.x, c[5] + bz1.y, c[6] + bz1.z, c[7] + bz1.w);
            if (EPI == 2) {
                o0.x = gelu_tanh(o0.x); o0.y = gelu_tanh(o0.y);
                o0.z = gelu_tanh(o0.z); o0.w = gelu_tanh(o0.w);
                o1.x = gelu_tanh(o1.x); o1.y = gelu_tanh(o1.y);
                o1.z = gelu_tanh(o1.z); o1.w = gelu_tanh(o1.w);
            }
            size_t rowoff = (size_t)(bm + m0 + hf) * 256;
            *(float4*)&C[rowoff + bn + (tx << 2)] = o0;
            *(float4*)&C[rowoff + bn + 64 + (tx << 2)] = o1;
        }
    }
}

// ---------------------------------------------------------------------------
// Flash attention via FFMA2, double-buffered K/V + bit-packed mask.
// Grid: (NQ/128, H, B), 256 threads. Q tile 128, K/V chunk 64, dh 64.
// ---------------------------------------------------------------------------
#define ATT_SMEM ((64 * 132 + 2 * 64 * 68 + 2 * 64 * 68 + 128 * 68) * (int)sizeof(float))

__global__ void __launch_bounds__(256, 1)
attn128(const float* __restrict__ Qm,
        const float* __restrict__ Km,
        const float* __restrict__ Vm,
        const unsigned* __restrict__ mbits,
        float* __restrict__ ctx) {
    extern __shared__ float sm[];
    float* Qs = sm;                 // [64][132]  d-major
    float* Ks = Qs + 64 * 132;      // [2][64][68] d-major
    float* Vs = Ks + 2 * 64 * 68;   // [2][64][68] k-major
    float* Ps = Vs + 2 * 64 * 68;   // [128][68]

    const int t = threadIdx.x;
    const int tx = t & 15, ty = t >> 4;
    const int b = blockIdx.z, h = blockIdx.y, q0 = blockIdx.x << 7;

    // load Q tile transposed: Qs[d][q]
#pragma unroll
    for (int r = 0; r < 8; r++) {
        int id = t + (r << 8);
        int q = id >> 4, dq = (id & 15) << 2;
        float4 v = *(const float4*)&Qm[((size_t)(b * NQS + q0 + q)) * 256 + h * 64 + dq];
        Qs[(dq + 0) * 132 + q] = v.x; Qs[(dq + 1) * 132 + q] = v.y;
        Qs[(dq + 2) * 132 + q] = v.z; Qs[(dq + 3) * 132 + q] = v.w;
    }

    float mrow[8], lrow[8];
    unsigned long long cacc[8][2];
#pragma unroll
    for (int i = 0; i < 8; i++) {
        mrow[i] = -3.0e38f; lrow[i] = 0.f;
        cacc[i][0] = 0ULL; cacc[i][1] = 0ULL;
    }

    float4 kreg[4];
    // prologue: chunk 0
#pragma unroll
    for (int r = 0; r < 4; r++) {
        int id = t + (r << 8);
        int kk = id >> 4, dq = (id & 15) << 2;
        size_t off = ((size_t)(b * NKS + kk)) * 256 + h * 64 + dq;
        kreg[r] = *(const float4*)&Km[off];
        cp16(&Vs[kk * 68 + dq], &Vm[off]);
    }
    cp_commit();
#pragma unroll
    for (int r = 0; r < 4; r++) {
        int id = t + (r << 8);
        int kk = id >> 4, dq = (id & 15) << 2;
        Ks[(dq + 0) * 68 + kk] = kreg[r].x; Ks[(dq + 1) * 68 + kk] = kreg[r].y;
        Ks[(dq + 2) * 68 + kk] = kreg[r].z; Ks[(dq + 3) * 68 + kk] = kreg[r].w;
    }
    cp_waitall();
    __syncthreads();

    int cur = 0;
#pragma unroll 1
    for (int c = 0; c < 16; c++) {
        const int k0 = c << 6;
        // prefetch mask bits (1 word per row)
        unsigned mb[8];
#pragma unroll
        for (int i = 0; i < 8; i++) {
            int rq = (i < 4) ? (ty << 2) + i : 64 + (ty << 2) + (i - 4);
            mb[i] = __ldg(&mbits[(size_t)(q0 + rq) * (NKS / 32) + (k0 >> 5) + (tx >> 3)]);
        }
        // prefetch next K/V chunk
        if (c < 15) {
#pragma unroll
            for (int r = 0; r < 4; r++) {
                int id = t + (r << 8);
                int kk = id >> 4, dq = (id & 15) << 2;
                size_t off = ((size_t)(b * NKS + k0 + 64 + kk)) * 256 + h * 64 + dq;
                kreg[r] = *(const float4*)&Km[off];
                cp16(&Vs[(cur ^ 1) * 4352 + kk * 68 + dq], &Vm[off]);
            }
            cp_commit();
        }

        const float* Kc = Ks + cur * 4352;
        const float* Vc = Vs + cur * 4352;

        // S = Q K^T
        unsigned long long s2[4][4];
#pragma unroll
        for (int p = 0; p < 4; p++)
#pragma unroll
            for (int j = 0; j < 4; j++) s2[p][j] = 0ULL;
#pragma unroll 16
        for (int d = 0; d < 64; d++) {
            ulonglong2 qa = *(const ulonglong2*)&Qs[d * 132 + (ty << 2)];
            ulonglong2 qb = *(const ulonglong2*)&Qs[d * 132 + 64 + (ty << 2)];
            float4 kv = *(const float4*)&Kc[d * 68 + (tx << 2)];
            unsigned long long kd[4] = {dup2f(kv.x), dup2f(kv.y), dup2f(kv.z), dup2f(kv.w)};
            unsigned long long qp[4] = {qa.x, qa.y, qb.x, qb.y};
#pragma unroll
            for (int p = 0; p < 4; p++)
#pragma unroll
                for (int j = 0; j < 4; j++) ffma2(s2[p][j], qp[p], kd[j]);
        }

        // unpack, mask, online softmax, store P, rescale acc
        const int sh = (tx & 7) << 2;
#pragma unroll
        for (int i = 0; i < 8; i++) {
            int rq = (i < 4) ? (ty << 2) + i : 64 + (ty << 2) + (i - 4);
            float sf[4];
#pragma unroll
            for (int j = 0; j < 4; j++) {
                float2 f = upk2(s2[i >> 1][j]);
                sf[j] = (i & 1) ? f.y : f.x;
            }
#pragma unroll
            for (int j = 0; j < 4; j++)
                sf[j] = ((mb[i] >> (sh + j)) & 1u) ? sf[j] * ATT_SCALE : -1.0e9f;
            float rm = fmaxf(fmaxf(sf[0], sf[1]), fmaxf(sf[2], sf[3]));
#pragma unroll
            for (int o = 1; o < 16; o <<= 1) rm = fmaxf(rm, __shfl_xor_sync(0xffffffffu, rm, o));
            float mn = fmaxf(mrow[i], rm);
            float corr = __expf(mrow[i] - mn);
            mrow[i] = mn;
            float rs = 0.f;
#pragma unroll
            for (int j = 0; j < 4; j++) {
                float p = __expf(sf[j] - mn);
                sf[j] = p;
                rs += p;
            }
#pragma unroll
            for (int o = 1; o < 16; o <<= 1) rs += __shfl_xor_sync(0xffffffffu, rs, o);
            lrow[i] = lrow[i] * corr + rs;
            unsigned long long cd = dup2f(corr);
            fmul2(cacc[i][0], cd);
            fmul2(cacc[i][1], cd);
            *(float4*)&Ps[rq * 68 + (tx << 2)] = make_float4(sf[0], sf[1], sf[2], sf[3]);
        }
        __syncwarp();   // P rows produced & consumed within one warp

        // ctx += P @ V
#pragma unroll 2
        for (int kk = 0; kk < 64; kk += 4) {
            float pk[8][4];
#pragma unroll
            for (int i = 0; i < 8; i++) {
                int rq = (i < 4) ? (ty << 2) + i : 64 + (ty << 2) + (i - 4);
                float4 p4 = *(const float4*)&Ps[rq * 68 + kk];
                pk[i][0] = p4.x; pk[i][1] = p4.y; pk[i][2] = p4.z; pk[i][3] = p4.w;
            }
#pragma unroll
            for (int u = 0; u < 4; u++) {
                ulonglong2 vv = *(const ulonglong2*)&Vc[(kk + u) * 68 + (tx << 2)];
#pragma unroll
                for (int i = 0; i < 8; i++) {
                    unsigned long long pd = dup2f(pk[i][u]);
                    ffma2(cacc[i][0], pd, vv.x);
                    ffma2(cacc[i][1], pd, vv.y);
                }
            }
        }

        if (c < 15) {
            float* Kn = Ks + (cur ^ 1) * 4352;
#pragma unroll
            for (int r = 0; r < 4; r++) {
                int id = t + (r << 8);
                int kk = id >> 4, dq = (id & 15) << 2;
                Kn[(dq + 0) * 68 + kk] = kreg[r].x; Kn[(dq + 1) * 68 + kk] = kreg[r].y;
                Kn[(dq + 2) * 68 + kk] = kreg[r].z; Kn[(dq + 3) * 68 + kk] = kreg[r].w;
            }
            cp_waitall();
            __syncthreads();
            cur ^= 1;
        }
    }

    // normalize and write ctx
#pragma unroll
    for (int i = 0; i < 8; i++) {
        int rq = (i < 4) ? (ty << 2) + i : 64 + (ty << 2) + (i - 4);
        float inv = 1.0f / lrow[i];
        float2 u0 = upk2(cacc[i][0]);
        float2 u1 = upk2(cacc[i][1]);
        float4 o = make_float4(u0.x * inv, u0.y * inv, u1.x * inv, u1.y * inv);
        *(float4*)&ctx[((size_t)(b * NQS + q0 + rq)) * 256 + h * 64 + (tx << 2)] = o;
    }
}

// ---------------------------------------------------------------------------
// Host launcher
// ---------------------------------------------------------------------------
extern "C" void kernel_launch(void* const* d_in, const int* in_sizes, int n_in,
                              void* d_out, int out_size) {
    const float* upd_in = (const float*)d_in[0];
    const float* emb    = (const float*)d_in[1];
    const float* maskL  = (const float*)d_in[2];
    const float* Wq     = (const float*)d_in[3];
    const float* Wk     = (const float*)d_in[4];
    const float* Wv     = (const float*)d_in[5];
    const float* Wo     = (const float*)d_in[6];
    const float* W1     = (const float*)d_in[7];
    const float* b1     = (const float*)d_in[8];
    const float* W2     = (const float*)d_in[9];
    const float* b2     = (const float*)d_in[10];
    const float* sys_s  = (const float*)d_in[11];
    const float* sys_b  = (const float*)d_in[12];
    const float* eff_s  = (const float*)d_in[13];
    const float* eff_b  = (const float*)d_in[14];
    const float* in_s   = (const float*)d_in[15];
    const float* in_b   = (const float*)d_in[16];
    const float* out_s  = (const float*)d_in[17];
    const float* out_b  = (const float*)d_in[18];
    const int*   qidx   = (const int*)d_in[19];
    const int*   kidx   = (const int*)d_in[20];
    float* out = (float*)d_out;

    float *p_upd, *p_q, *p_k, *p_Qp, *p_Kp, *p_Vp, *p_ctx, *p_t1, *p_h, *p_gl, *p_f;
    unsigned* p_mb;
    cudaGetSymbolAddress((void**)&p_upd, g_upd);
    cudaGetSymbolAddress((void**)&p_q,   g_q);
    cudaGetSymbolAddress((void**)&p_k,   g_k);
    cudaGetSymbolAddress((void**)&p_Qp,  g_Qp);
    cudaGetSymbolAddress((void**)&p_Kp,  g_Kp);
    cudaGetSymbolAddress((void**)&p_Vp,  g_Vp);
    cudaGetSymbolAddress((void**)&p_ctx, g_ctx);
    cudaGetSymbolAddress((void**)&p_t1,  g_t1);
    cudaGetSymbolAddress((void**)&p_h,   g_h);
    cudaGetSymbolAddress((void**)&p_gl,  g_gl);
    cudaGetSymbolAddress((void**)&p_f,   g_f);
    cudaGetSymbolAddress((void**)&p_mb,  g_mb);

    cudaFuncSetAttribute(gemm2_db<0>, cudaFuncAttributeMaxDynamicSharedMemorySize, GEMM_SMEM);
    cudaFuncSetAttribute(gemm2_db<1>, cudaFuncAttributeMaxDynamicSharedMemorySize, GEMM_SMEM);
    cudaFuncSetAttribute(gemm2_db<2>, cudaFuncAttributeMaxDynamicSharedMemorySize, GEMM_SMEM);
    cudaFuncSetAttribute(attn128, cudaFuncAttributeMaxDynamicSharedMemorySize, ATT_SMEM);

    const size_t n_upd = (size_t)BB * NSZ * DD;
    init_kernel<<<2048, 256>>>(p_upd, out, upd_in, n_upd / 4);

    const int MQ = BB * NQS;    // 16384
    const int MK = BB * NKS;    // 32768

    for (int l = 0; l < LLV; l++) {
        const int* qi = qidx + l * NQS;
        const int* ki = kidx + l * NKS;
        const float* mk = maskL + (size_t)l * NQS * NKS;

        pack_mask_kernel<<<(NQS * NKS / 32) / 256, 256>>>(mk, p_mb);

        gather_ln_w<<<MQ / 8, 256>>>(emb, qi, sys_s, sys_b, p_upd, p_q, 9);
        gather_ln_w<<<MK / 8, 256>>>(emb, ki, sys_s, sys_b, p_upd, p_k, 10);

        gemm2_db<0><<<dim3(MQ >> 7, 2), 256, GEMM_SMEM>>>(p_q, Wq, nullptr, p_Qp);
        gemm2_db<0><<<dim3(MK >> 7, 2), 256, GEMM_SMEM>>>(p_k, Wk, nullptr, p_Kp);
        gemm2_db<0><<<dim3(MK >> 7, 2), 256, GEMM_SMEM>>>(p_k, Wv, nullptr, p_Vp);

        attn128<<<dim3(NQS / 128, HH, BB), 256, ATT_SMEM>>>(p_Qp, p_Kp, p_Vp, p_mb, p_ctx);

        gemm2_db<0><<<dim3(MQ >> 7, 2), 256, GEMM_SMEM>>>(p_ctx, Wo, nullptr, p_t1);
        ln_rows_w<<<MQ / 8, 256>>>(p_t1, in_s, in_b, p_h);

        gemm2_db<2><<<dim3(MQ >> 7, 2), 256, GEMM_SMEM>>>(p_h, W1, b1, p_gl);
        gemm2_db<1><<<dim3(MQ >> 7, 2), 256, GEMM_SMEM>>>(p_gl, W2, b2, p_f);

        dln_scatter_w<<<MQ / 8, 256>>>(p_h, p_f, out_s, out_b, eff_s, eff_b,
                                       qi, p_upd, out);
    }
}